// round 10
// baseline (speedup 1.0000x reference)
#include <cuda_runtime.h>
#include <stdint.h>

#define N_ANCH   25200
#define NDIM     85
#define NCLS     80
#define TOPK     1000
#define NB_MAX   32
#define NBINS    4096
#define BCAP     16
#define CAND     2048              // rescue sort size (power of 2)
#define FLOORF   0.9375f           // capture floor; bins span [0.9375, 1)
#define BINSCALE 65536.0f          // 4096 / 0.0625
#define K1_THREADS 256
#define K1_MLP     2
#define BLK_ITEMS  (K1_THREADS * K1_MLP)                  // 512
#define NBLK       ((N_ANCH + BLK_ITEMS - 1) / BLK_ITEMS) // 50
#define NPT        25              // rescue: ceil(25200/1024)
#define ROWS_PER_CTA 25            // k3: 40 CTAs/batch x 25 rows

__device__ unsigned int       g_hist[NB_MAX][NBINS];      // zero-init; K2 re-zeroes
__device__ unsigned long long g_bucket[NB_MAX][NBINS * BCAP];
__device__ unsigned long long g_cand[NB_MAX][TOPK];       // rank-ordered keys

// ---------------- K1: pure scan; capture only items >= FLOORF ----------------
__global__ __launch_bounds__(K1_THREADS) void k1_scan(const float* __restrict__ pred) {
    const int b  = blockIdx.y;
    const int i0 = blockIdx.x * BLK_ITEMS;
    const float* base = pred + (size_t)b * N_ANCH * NDIM;

    float v[K1_MLP];
    int   idx[K1_MLP];
#pragma unroll
    for (int s = 0; s < K1_MLP; s++) {       // batch the loads
        idx[s] = i0 + s * K1_THREADS + threadIdx.x;
        v[s] = (idx[s] < N_ANCH) ? __ldcg(base + (size_t)idx[s] * NDIM + 4) : 0.0f;
    }
#pragma unroll
    for (int s = 0; s < K1_MLP; s++) {
        float f = v[s];
        if (idx[s] >= N_ANCH || !(f >= FLOORF)) continue;   // ~97% exit here
        int bin = (int)((f - FLOORF) * BINSCALE);
        bin = min(max(bin, 0), NBINS - 1);
        unsigned int pos = atomicAdd(&g_hist[b][bin], 1u);
        if (pos < BCAP)
            g_bucket[b][bin * BCAP + pos] =
                ((unsigned long long)__float_as_uint(f) << 32) |
                (unsigned int)(~(unsigned int)idx[s]);
    }
#if __CUDA_ARCH__ >= 900
    cudaTriggerProgrammaticLaunchCompletion();   // release k2 as CTAs drain
#endif
}

// ---------------- K2: exact global rank per candidate -> g_cand[rank] ----------------
__global__ __launch_bounds__(1024) void k2_select(const float* __restrict__ pred) {
    __shared__ unsigned int s_suf[1024];
    __shared__ unsigned int s_wsum[32], s_wsuf[32];
    __shared__ int s_tbin, s_pos, s_flag;
    __shared__ unsigned int s_hist256[256];
    __shared__ unsigned int s_sel, s_k;
    __shared__ unsigned long long s_keys[CAND];   // rescue only

    const int b = blockIdx.x, tid = threadIdx.x, lane = tid & 31, w = tid >> 5;

#if __CUDA_ARCH__ >= 900
    cudaGridDependencySynchronize();    // PDL: wait for k1's writes before reading
#endif

    // load my 4 contiguous bins (vectorized), then immediately re-zero them
    uint4 h4 = ((uint4*)g_hist[b])[tid];
    ((uint4*)g_hist[b])[tid] = make_uint4(0, 0, 0, 0);
    unsigned int loc[4] = {h4.x, h4.y, h4.z, h4.w};
    unsigned int tot = loc[0] + loc[1] + loc[2] + loc[3];

    // ---- suffix scan via shuffles ----
    unsigned int vsc = tot;
#pragma unroll
    for (int off = 1; off < 32; off <<= 1) {     // intra-warp inclusive suffix scan
        unsigned int t = __shfl_down_sync(0xffffffffu, vsc, off);
        if (lane + off < 32) vsc += t;
    }
    if (lane == 0) s_wsum[w] = vsc;              // warp total
    if (tid == 0) { s_pos = 0; s_flag = 0; }
    __syncthreads();
    if (w == 0) {                                // warp 0 scans the 32 warp sums
        unsigned int wv = s_wsum[lane];
#pragma unroll
        for (int off = 1; off < 32; off <<= 1) {
            unsigned int t = __shfl_down_sync(0xffffffffu, wv, off);
            if (lane + off < 32) wv += t;
        }
        s_wsuf[lane] = wv;                       // sum of warp totals [lane..31]
    }
    __syncthreads();
    s_suf[tid] = vsc + ((w < 31) ? s_wsuf[w + 1] : 0u);
    __syncthreads();
    const unsigned int total = s_suf[0];         // items >= FLOORF

    if (total >= TOPK) {
        unsigned int S = s_suf[tid];
#pragma unroll
        for (int i = 0; i < 4; i++) {
            if (S >= TOPK && S - loc[i] < TOPK)      // unique crossing bin
                s_tbin = tid * 4 + i;
            S -= loc[i];
        }
    } else if (tid == 0) s_flag = 1;
    __syncthreads();
    const int tbin = s_tbin;

    bool ovf = false;
#pragma unroll
    for (int i = 0; i < 4; i++)
        ovf |= (tid * 4 + i >= tbin) && (loc[i] > BCAP);
    if (__syncthreads_or(ovf)) { if (tid == 0) s_flag = 1; }
    __syncthreads();

    if (!s_flag) {
        unsigned int acc = (tid < 1023) ? s_suf[tid + 1] : 0u;
        unsigned int gt[4];
#pragma unroll
        for (int i = 3; i >= 0; i--) { gt[i] = acc; acc += loc[i]; }

#pragma unroll
        for (int i = 0; i < 4; i++) {
            const int bin = tid * 4 + i;
            const int c = (int)loc[i];
            if (bin < tbin || c == 0 || gt[i] >= TOPK) continue;
            unsigned long long kk[BCAP];
            for (int j = 0; j < c; j++) kk[j] = g_bucket[b][bin * BCAP + j];
            for (int j = 0; j < c; j++) {        // in-bin rank: (value desc, idx asc)
                int r = (int)gt[i];
                for (int m = 0; m < c; m++) r += (kk[m] > kk[j]);
                if (r < TOPK) g_cand[b][r] = kk[j];
            }
        }
#if __CUDA_ARCH__ >= 900
        cudaTriggerProgrammaticLaunchCompletion();
#endif
        return;
    }

    // ---------- rescue: exact radix select + bitonic sort (never on this data) ----------
    const float* base = pred + (size_t)b * N_ANCH * NDIM;
    unsigned int rv[NPT];
#pragma unroll
    for (int s = 0; s < NPT; s++) {
        int i = s * 1024 + tid;
        rv[s] = (i < N_ANCH)
              ? __float_as_uint(__ldcg(base + (size_t)i * NDIM + 4)) : 0u;
    }
    if (tid == 0) s_k = TOPK;
    __syncthreads();
    unsigned int prefix = 0, prefmask = 0;
    for (int pass = 0; pass < 4; pass++) {
        const int shift = 24 - 8 * pass;
        if (tid < 256) s_hist256[tid] = 0;
        __syncthreads();
#pragma unroll
        for (int s = 0; s < NPT; s++) {
            int i = s * 1024 + tid;
            bool ok = (i < N_ANCH) && ((rv[s] & prefmask) == prefix);
            unsigned int digit = ok ? ((rv[s] >> shift) & 255u) : 0xffffffffu;
            unsigned int m = __match_any_sync(0xffffffffu, digit);
            if (ok && lane == (__ffs(m) - 1))
                atomicAdd(&s_hist256[digit], (unsigned int)__popc(m));
        }
        __syncthreads();
        unsigned int kcur = s_k;
        __syncthreads();
        for (int off = 1; off < 256; off <<= 1) {
            unsigned int t = 0;
            if (tid < 256 && tid + off < 256) t = s_hist256[tid + off];
            __syncthreads();
            if (tid < 256) s_hist256[tid] += t;
            __syncthreads();
        }
        if (tid < 256) {
            unsigned int ge = s_hist256[tid];
            unsigned int gtv = (tid == 255) ? 0u : s_hist256[tid + 1];
            if (ge >= kcur && gtv < kcur) { s_sel = (unsigned int)tid; s_k = kcur - gtv; }
        }
        __syncthreads();
        prefix   |= s_sel << shift;
        prefmask |= 255u << shift;
        __syncthreads();
    }
#pragma unroll
    for (int s = 0; s < NPT; s++) {
        int i = s * 1024 + tid;
        if (i < N_ANCH && rv[s] >= prefix) {
            int p = atomicAdd(&s_pos, 1);
            if (p < CAND)
                s_keys[p] = ((unsigned long long)rv[s] << 32) |
                            (unsigned int)(~(unsigned int)i);
        }
    }
    __syncthreads();
    int cnt = min(s_pos, CAND);
    for (int i = tid; i < CAND; i += 1024)
        if (i >= cnt) s_keys[i] = 0ull;          // padding sorts last
    __syncthreads();
    for (int ksz = 2; ksz <= CAND; ksz <<= 1) {  // bitonic sort, descending
        for (int j = ksz >> 1; j > 0; j >>= 1) {
            for (int t = tid; t < CAND; t += 1024) {
                int l = t ^ j;
                if (l > t) {
                    unsigned long long a = s_keys[t], c2 = s_keys[l];
                    bool sw = ((t & ksz) == 0) ? (a < c2) : (a > c2);
                    if (sw) { s_keys[t] = c2; s_keys[l] = a; }
                }
            }
            __syncthreads();
        }
    }
    if (tid < TOPK) g_cand[b][tid] = s_keys[tid];
    if (tid + 1024 < TOPK) g_cand[b][tid + 1024] = s_keys[tid + 1024];
#if __CUDA_ARCH__ >= 900
    cudaTriggerProgrammaticLaunchCompletion();
#endif
}

// ---------------- K3: single-wave gather + emit (4 rows per warp, MLP-batched) ----------------
// grid (40, B), 256 threads: CTA owns 25 rows; warp w owns rows base + w + 8j, j<4.
__global__ __launch_bounds__(256) void k3_emit(const float* __restrict__ pred,
                                               float* __restrict__ scores_out,
                                               float* __restrict__ boxes_out) {
    const int b = blockIdx.y;
    const int w = threadIdx.x >> 5, lane = threadIdx.x & 31;
    const int base = blockIdx.x * ROWS_PER_CTA;

#if __CUDA_ARCH__ >= 900
    cudaGridDependencySynchronize();    // PDL: wait for k2's g_cand before reading
#endif

    // phase 1: prefetch this warp's keys (lane j<4 loads key for row base+w+8j)
    unsigned long long mykey = 0ull;
    if (lane < 4) {
        int rr = base + w + 8 * lane;
        if (w + 8 * lane < ROWS_PER_CTA && rr < TOPK)
            mykey = g_cand[b][rr];
    }

    const float* batch = pred + (size_t)b * N_ANCH * NDIM;
    const int nrows = (ROWS_PER_CTA - w + 7) >> 3;     // 4 for w=0, else 3

    // phase 2: issue ALL gather loads into registers (high MLP)
    float cls[4][3];
    float bxy[4], bwh[4];
    float validv[4];
    int   rowidx[4];
#pragma unroll
    for (int j = 0; j < 4; j++) {
        if (j >= nrows) break;                         // warp-uniform
        unsigned long long key = __shfl_sync(0xffffffffu, mykey, j);
        const int idx = (int)(~(unsigned int)key);
        const float val = __uint_as_float((unsigned int)(key >> 32));
        validv[j] = (val > 0.25f) ? val : 0.0f;
        rowidx[j] = base + w + 8 * j;
        const float* row = batch + (size_t)idx * NDIM;
#pragma unroll
        for (int k = 0; k < 3; k++) {
            int c = lane + 32 * k;
            cls[j][k] = (c < NCLS) ? row[5 + c] : 0.0f;
        }
        if (lane < 4) {                                // lanes 0,1: xy; 2,3 reuse
            bxy[j] = row[lane & 1];
            bwh[j] = row[2 + (lane & 1)];
        }
    }

    // phase 3: coalesced stores
#pragma unroll
    for (int j = 0; j < 4; j++) {
        if (j >= nrows) break;
        const int r = rowidx[j];
        float* srow = scores_out + ((size_t)b * TOPK + r) * NCLS;
#pragma unroll
        for (int k = 0; k < 3; k++) {
            int c = lane + 32 * k;
            if (c < NCLS) {
                float m = cls[j][k] * validv[j];
                srow[c] = (m > 0.25f) ? m : 0.0f;
            }
        }
        if (lane < 4) {                                // xywh -> xyxy
            float half = bwh[j] * 0.5f;
            float o = (lane < 2) ? (bxy[j] - half) : (bxy[j] + half);
            boxes_out[((size_t)b * TOPK + r) * 4 + lane] = o;
        }
    }
}

extern "C" void kernel_launch(void* const* d_in, const int* in_sizes, int n_in,
                              void* d_out, int out_size) {
    const float* pred = (const float*)d_in[0];
    const int B = in_sizes[0] / (N_ANCH * NDIM);

    float* scores = (float*)d_out;                       // (B, TOPK, NCLS)
    float* boxes  = scores + (size_t)B * TOPK * NCLS;    // (B, TOPK, 4)

    k1_scan<<<dim3(NBLK, B), K1_THREADS>>>(pred);

    cudaLaunchAttribute attr[1];
    attr[0].id = cudaLaunchAttributeProgrammaticStreamSerialization;
    attr[0].val.programmaticStreamSerializationAllowed = 1;

    {
        cudaLaunchConfig_t cfg = {};
        cfg.gridDim  = dim3(B, 1, 1);
        cfg.blockDim = dim3(1024, 1, 1);
        cfg.attrs = attr;
        cfg.numAttrs = 1;
        cudaLaunchKernelEx(&cfg, k2_select, pred);
    }
    {
        cudaLaunchConfig_t cfg = {};
        cfg.gridDim  = dim3((TOPK + ROWS_PER_CTA - 1) / ROWS_PER_CTA, B, 1);
        cfg.blockDim = dim3(256, 1, 1);
        cfg.attrs = attr;
        cfg.numAttrs = 1;
        cudaLaunchKernelEx(&cfg, k3_emit, pred, scores, boxes);
    }
}